// round 11
// baseline (speedup 1.0000x reference)
#include <cuda_runtime.h>
#include <cuda_fp16.h>
#include <cstdint>

#define BATCH 4
#define NSEQ  2048
#define DIM   512
#define NHEAD 8
#define HDIM  64
#define ROWS  (BATCH * NSEQ)   // 8192

// ---------------- scratch (static device globals; no allocations) ----------
__device__ float  g_hcat [ROWS * 2 * DIM];     // fp32 pre-LN
__device__ __half g_qkvh [ROWS * 3 * DIM];     // fp16 pre-RoPE
__device__ __half g_xh   [ROWS * DIM];
__device__ __half g_wqkvh[512 * 1536];
__device__ __half g_outwh[512 * 512];
__device__ __half g_ffn1h[1024 * 1024];
__device__ __half g_ffn2h[1024 * 512];
__device__ __half g_qh   [ROWS * DIM];         // [BH][N][64], pre-scaled
__device__ __half g_kh   [ROWS * DIM];
__device__ __half g_vh   [ROWS * DIM];
__device__ __half g_atth [ROWS * DIM];         // [B,N,D] fp16
__device__ __half g_msgh [ROWS * DIM];
__device__ __half g_hcath[ROWS * 2 * DIM];

// ---------------------------------------------------------------------------
#define CP_ASYNC_CG(dst, src) \
    asm volatile("cp.async.cg.shared.global [%0], [%1], 16;" :: "r"(dst), "l"(src))
#define CP_COMMIT() asm volatile("cp.async.commit_group;")
#define CP_WAIT(n)  asm volatile("cp.async.wait_group %0;" :: "n"(n))

__device__ __forceinline__ unsigned smem_u32(const void* p) {
    unsigned a;
    asm("{ .reg .u64 t; cvta.to.shared.u64 t, %1; cvt.u32.u64 %0, t; }"
        : "=r"(a) : "l"(p));
    return a;
}

#define LDSM_X4(r0, r1, r2, r3, addr) \
    asm volatile("ldmatrix.sync.aligned.m8n8.x4.shared.b16 {%0,%1,%2,%3}, [%4];" \
                 : "=r"(r0), "=r"(r1), "=r"(r2), "=r"(r3) : "r"(addr))
#define LDSM_X4_T(r0, r1, r2, r3, addr) \
    asm volatile("ldmatrix.sync.aligned.m8n8.x4.trans.shared.b16 {%0,%1,%2,%3}, [%4];" \
                 : "=r"(r0), "=r"(r1), "=r"(r2), "=r"(r3) : "r"(addr))

__device__ __forceinline__ void mma16(float* d, const unsigned* a,
                                      unsigned b0, unsigned b1) {
    asm volatile(
        "mma.sync.aligned.m16n8k16.row.col.f32.f16.f16.f32 "
        "{%0,%1,%2,%3},{%4,%5,%6,%7},{%8,%9},{%0,%1,%2,%3};\n"
        : "+f"(d[0]), "+f"(d[1]), "+f"(d[2]), "+f"(d[3])
        : "r"(a[0]), "r"(a[1]), "r"(a[2]), "r"(a[3]), "r"(b0), "r"(b1));
}

__device__ __forceinline__ __half2 h2(float a, float b) {
    return __floats2half2_rn(a, b);
}

__device__ __forceinline__ unsigned pack_h2(float a, float b) {
    __half2 h = __floats2half2_rn(a, b);
    return *(unsigned*)&h;
}

// ---------------------------------------------------------------------------
// fp32 -> fp16 convert (n % 1024 == 0).
// ---------------------------------------------------------------------------
__global__ __launch_bounds__(256) void cvt16_kernel(
    const float* __restrict__ in, __half* __restrict__ out)
{
    const int i = (blockIdx.x * 256 + threadIdx.x) * 4;
    float4 v = *(const float4*)(in + i);
    *(__half2*)(out + i)     = h2(v.x, v.y);
    *(__half2*)(out + i + 2) = h2(v.z, v.w);
}

// ---------------------------------------------------------------------------
// fp16 GEMM v2: 256x128 CTA tile, 8 warps (4m x 2n) of 64x64, BK=32,
// 4-stage cp.async pipeline (empty-commit trick keeps group count fixed).
// A fp16 split at `ksplit` (A0/A1), B fp16 [K][N].  Out: C32 and/or C16.
// Dyn smem: 4 stages x (A 256x40 + B 32x136) halves = 116736 B -> 1 CTA/SM.
// ---------------------------------------------------------------------------
#define GSTG   (256 * 40 + 32 * 136)        // halves per stage (14592)
#define GSMEM  (4 * GSTG * 2)               // 116736 B

__global__ __launch_bounds__(256) void gemm_f16(
    const __half* __restrict__ A0, int lda0,
    const __half* __restrict__ A1, int lda1, int ksplit,
    const __half* __restrict__ B,
    const float* __restrict__ bias,
    const float* __restrict__ resid,
    float* __restrict__ C32, __half* __restrict__ C16, int N, int K)
{
    extern __shared__ __half gsm[];
    const unsigned uS = smem_u32(gsm);

    const int tid  = threadIdx.x;
    const int warp = tid >> 5;
    const int lane = tid & 31;
    const int g    = lane >> 2;
    const int tg   = lane & 3;
    const int wm   = (warp >> 1) * 64;     // 0,64,128,192
    const int wn   = (warp & 1) * 64;      // 0,64

    const int bm = blockIdx.y * 256;
    const int bn = blockIdx.x * 128;

    float acc[4][8][4];
#pragma unroll
    for (int mt = 0; mt < 4; mt++)
#pragma unroll
        for (int nt = 0; nt < 8; nt++)
#pragma unroll
            for (int c = 0; c < 4; c++) acc[mt][nt][c] = 0.0f;

    const int NT = K >> 5;

    auto prefetch = [&](int t, int s) {
        const int k0 = t << 5;
        const unsigned uA = uS + (s * GSTG) * 2;
        const unsigned uB = uA + (256 * 40) * 2;
#pragma unroll
        for (int i = 0; i < 4; i++) {        // A: 256 rows x 32 cols
            const int idx = i * 256 + tid;   // 0..1023
            const int r   = idx >> 2;        // 0..255
            const int c8  = (idx & 3) << 3;  // 0,8,16,24
            const __half* ap = (k0 < ksplit)
                ? A0 + (size_t)(bm + r) * lda0 + k0 + c8
                : A1 + (size_t)(bm + r) * lda1 + (k0 - ksplit) + c8;
            CP_ASYNC_CG(uA + (r * 40 + c8) * 2, ap);
        }
#pragma unroll
        for (int i = 0; i < 2; i++) {        // B: 32 rows x 128 cols
            const int idx = i * 256 + tid;   // 0..511
            const int r   = idx >> 4;        // 0..31
            const int c8  = (idx & 15) << 3; // 0..120
            CP_ASYNC_CG(uB + (r * 136 + c8) * 2,
                        B + (size_t)(k0 + r) * N + bn + c8);
        }
    };

    prefetch(0, 0); CP_COMMIT();
    prefetch(1, 1); CP_COMMIT();
    prefetch(2, 2); CP_COMMIT();

    for (int t = 0; t < NT; t++) {
        CP_WAIT(2);          // stage t's group retired (3 groups outstanding)
        __syncthreads();     // all warps done with stage t-1 (the refill target)
        if (t + 3 < NT) prefetch(t + 3, (t + 3) & 3);
        CP_COMMIT();         // possibly empty — keeps outstanding count at 3

        const unsigned aBase = uS + ((t & 3) * GSTG) * 2;
        const unsigned bBase = aBase + (256 * 40) * 2;

#pragma unroll
        for (int ks = 0; ks < 2; ks++) {
            unsigned af[4][4];
#pragma unroll
            for (int mt = 0; mt < 4; mt++) {
                const int row = wm + mt * 16 + (lane & 7) + ((lane >> 3) & 1) * 8;
                const int col = ks * 16 + (lane >> 4) * 8;
                LDSM_X4(af[mt][0], af[mt][1], af[mt][2], af[mt][3],
                        aBase + (row * 40 + col) * 2);
            }
            unsigned bf[4][4];
#pragma unroll
            for (int np = 0; np < 4; np++) {
                const int row = ks * 16 + (lane & 7) + ((lane >> 3) & 1) * 8;
                const int col = wn + np * 16 + (lane >> 4) * 8;
                LDSM_X4_T(bf[np][0], bf[np][1], bf[np][2], bf[np][3],
                          bBase + (row * 136 + col) * 2);
            }
#pragma unroll
            for (int mt = 0; mt < 4; mt++)
#pragma unroll
                for (int nt = 0; nt < 8; nt++)
                    mma16(acc[mt][nt], af[mt],
                          bf[nt >> 1][(nt & 1) * 2], bf[nt >> 1][(nt & 1) * 2 + 1]);
        }
    }

    // ---- epilogue ----
#pragma unroll
    for (int mt = 0; mt < 4; mt++) {
        const int r0 = bm + wm + mt * 16 + g;
#pragma unroll
        for (int nt = 0; nt < 8; nt++) {
            const int col = bn + wn + nt * 8 + tg * 2;
            float2 bb = *(const float2*)&bias[col];
            float2 v0, v1;
            v0.x = acc[mt][nt][0] + bb.x;
            v0.y = acc[mt][nt][1] + bb.y;
            v1.x = acc[mt][nt][2] + bb.x;
            v1.y = acc[mt][nt][3] + bb.y;
            const size_t o0 = (size_t)r0 * N + col;
            const size_t o1 = (size_t)(r0 + 8) * N + col;
            if (resid) {
                float2 rr0 = *(const float2*)&resid[o0];
                float2 rr1 = *(const float2*)&resid[o1];
                v0.x += rr0.x; v0.y += rr0.y;
                v1.x += rr1.x; v1.y += rr1.y;
            }
            if (C32) {
                *(float2*)&C32[o0] = v0;
                *(float2*)&C32[o1] = v1;
            }
            if (C16) {
                *(__half2*)&C16[o0] = h2(v0.x, v0.y);
                *(__half2*)&C16[o1] = h2(v1.x, v1.y);
            }
        }
    }
}

// ---------------------------------------------------------------------------
// RoPE + split + head transpose; fp16 in (qkv), fp16 out, math in fp32.
// ---------------------------------------------------------------------------
__global__ __launch_bounds__(256) void rope_kernel(
    const __half* __restrict__ qkv, const float* __restrict__ freqs,
    __half* __restrict__ Q, __half* __restrict__ K, __half* __restrict__ V)
{
    const int bn = blockIdx.x;
    const int b  = bn >> 11;
    const int h  = threadIdx.x >> 5;
    const int i  = threadIdx.x & 31;
    const int n  = bn & 2047;

    const float f = freqs[(size_t)bn * 32 + i];
    const float c = cosf(f), s = sinf(f);

    const __half* base = qkv + (size_t)bn * 1536;
    const int e = h * 64 + 2 * i;

    const float2 q2 = __half22float2(*(const __half2*)(base + e));
    const float2 k2 = __half22float2(*(const __half2*)(base + 512 + e));
    const __half2 v2 = *(const __half2*)(base + 1024 + e);

    const size_t oidx = (((size_t)(b * NHEAD + h)) * NSEQ + n) * 64 + 2 * i;
    *(__half2*)(Q + oidx) = h2((q2.x * c - q2.y * s) * 0.125f,
                               (q2.x * s + q2.y * c) * 0.125f);
    *(__half2*)(K + oidx) = h2(k2.x * c - k2.y * s, k2.x * s + k2.y * c);
    *(__half2*)(V + oidx) = v2;
}

// ---------------------------------------------------------------------------
// Flash attention, fp16 mma (m16n8k16), FA2 register path (unchanged).
// ---------------------------------------------------------------------------
#define ATT_SMEM ((128 * 72 + 2 * 64 * 72 + 2 * 64 * 72) * 2)

__global__ __launch_bounds__(128) void attn_f16(
    const __half* __restrict__ Qg_, const __half* __restrict__ Kg_,
    const __half* __restrict__ Vg_, __half* __restrict__ O)
{
    extern __shared__ __half hsm[];
    const unsigned uQ = smem_u32(hsm);
    const unsigned uK = uQ + 128 * 72 * 2;
    const unsigned uV = uK + 2 * 64 * 72 * 2;

    const int tid  = threadIdx.x;
    const int warp = tid >> 5;
    const int lane = tid & 31;
    const int g    = lane >> 2;
    const int tg   = lane & 3;
    const int band = warp * 32;

    const int bh    = blockIdx.y;
    const int qbase = blockIdx.x * 128;

    const __half* Qg = Qg_ + ((size_t)bh * NSEQ + qbase) * 64;
    const __half* Kg = Kg_ + (size_t)bh * NSEQ * 64;
    const __half* Vg = Vg_ + (size_t)bh * NSEQ * 64;

    auto prefetchKV = [&](int tile, int s) {
#pragma unroll
        for (int i = 0; i < 4; i++) {
            const int idx = i * 128 + tid;     // 0..511
            const int r   = idx >> 3;          // 0..63
            const int c8  = (idx & 7) << 3;
            const size_t off = (size_t)(tile * 64 + r) * 64 + c8;
            CP_ASYNC_CG(uK + (s * 64 * 72 + r * 72 + c8) * 2, Kg + off);
            CP_ASYNC_CG(uV + (s * 64 * 72 + r * 72 + c8) * 2, Vg + off);
        }
    };

#pragma unroll
    for (int i = 0; i < 8; i++) {
        const int idx = i * 128 + tid;
        const int r   = idx >> 3;
        const int c8  = (idx & 7) << 3;
        CP_ASYNC_CG(uQ + (r * 72 + c8) * 2, Qg + (size_t)r * 64 + c8);
    }
    prefetchKV(0, 0);
    CP_COMMIT();

    unsigned qf[2][4][4];
    float oacc[2][8][4];
#pragma unroll
    for (int mt = 0; mt < 2; mt++)
#pragma unroll
        for (int n = 0; n < 8; n++)
#pragma unroll
            for (int c = 0; c < 4; c++) oacc[mt][n][c] = 0.0f;
    float mst[2][2] = {{-1e30f, -1e30f}, {-1e30f, -1e30f}};
    float lst[2][2] = {{0.0f, 0.0f}, {0.0f, 0.0f}};

    const int NT = NSEQ / 64;
    for (int t = 0; t < NT; t++) {
        __syncthreads();
        if (t + 1 < NT) { prefetchKV(t + 1, (t + 1) & 1); CP_COMMIT(); CP_WAIT(1); }
        else            { CP_WAIT(0); }
        __syncthreads();

        if (t == 0) {
#pragma unroll
            for (int mt = 0; mt < 2; mt++)
#pragma unroll
                for (int ks = 0; ks < 4; ks++) {
                    const int row = band + mt * 16 + (lane & 7) + ((lane >> 3) & 1) * 8;
                    const int col = ks * 16 + (lane >> 4) * 8;
                    LDSM_X4(qf[mt][ks][0], qf[mt][ks][1], qf[mt][ks][2], qf[mt][ks][3],
                            uQ + (row * 72 + col) * 2);
                }
        }

        const unsigned cK = uK + ((t & 1) * 64 * 72) * 2;
        const unsigned cV = uV + ((t & 1) * 64 * 72) * 2;

        // ---- S = Q @ K^T ----
        float sacc[2][8][4];
#pragma unroll
        for (int mt = 0; mt < 2; mt++)
#pragma unroll
            for (int n = 0; n < 8; n++)
#pragma unroll
                for (int c = 0; c < 4; c++) sacc[mt][n][c] = 0.0f;

#pragma unroll
        for (int ks = 0; ks < 4; ks++) {
            unsigned kf[4][4];
#pragma unroll
            for (int kp = 0; kp < 4; kp++) {
                const int row = kp * 16 + (lane & 7) + (lane >> 4) * 8;
                const int col = ks * 16 + ((lane >> 3) & 1) * 8;
                LDSM_X4(kf[kp][0], kf[kp][1], kf[kp][2], kf[kp][3],
                        cK + (row * 72 + col) * 2);
            }
#pragma unroll
            for (int mt = 0; mt < 2; mt++)
#pragma unroll
                for (int n = 0; n < 8; n++)
                    mma16(sacc[mt][n], qf[mt][ks],
                          kf[n >> 1][(n & 1) * 2], kf[n >> 1][(n & 1) * 2 + 1]);
        }

        // ---- online softmax ----
#pragma unroll
        for (int mt = 0; mt < 2; mt++) {
            float r0 = -1e30f, r1 = -1e30f;
#pragma unroll
            for (int n = 0; n < 8; n++) {
                r0 = fmaxf(r0, fmaxf(sacc[mt][n][0], sacc[mt][n][1]));
                r1 = fmaxf(r1, fmaxf(sacc[mt][n][2], sacc[mt][n][3]));
            }
            r0 = fmaxf(r0, __shfl_xor_sync(0xffffffffu, r0, 1));
            r0 = fmaxf(r0, __shfl_xor_sync(0xffffffffu, r0, 2));
            r1 = fmaxf(r1, __shfl_xor_sync(0xffffffffu, r1, 1));
            r1 = fmaxf(r1, __shfl_xor_sync(0xffffffffu, r1, 2));

            const float mn0 = fmaxf(mst[mt][0], r0);
            const float mn1 = fmaxf(mst[mt][1], r1);
            const float c0 = __expf(mst[mt][0] - mn0);
            const float c1 = __expf(mst[mt][1] - mn1);

            float s0 = 0.0f, s1 = 0.0f;
#pragma unroll
            for (int n = 0; n < 8; n++) {
                sacc[mt][n][0] = __expf(sacc[mt][n][0] - mn0);
                sacc[mt][n][1] = __expf(sacc[mt][n][1] - mn0);
                sacc[mt][n][2] = __expf(sacc[mt][n][2] - mn1);
                sacc[mt][n][3] = __expf(sacc[mt][n][3] - mn1);
                s0 += sacc[mt][n][0] + sacc[mt][n][1];
                s1 += sacc[mt][n][2] + sacc[mt][n][3];
            }
            s0 += __shfl_xor_sync(0xffffffffu, s0, 1);
            s0 += __shfl_xor_sync(0xffffffffu, s0, 2);
            s1 += __shfl_xor_sync(0xffffffffu, s1, 1);
            s1 += __shfl_xor_sync(0xffffffffu, s1, 2);

            lst[mt][0] = lst[mt][0] * c0 + s0;
            lst[mt][1] = lst[mt][1] * c1 + s1;
#pragma unroll
            for (int n = 0; n < 8; n++) {
                oacc[mt][n][0] *= c0;  oacc[mt][n][1] *= c0;
                oacc[mt][n][2] *= c1;  oacc[mt][n][3] *= c1;
            }
            mst[mt][0] = mn0;  mst[mt][1] = mn1;
        }

        // ---- O += P @ V ----
#pragma unroll
        for (int ks = 0; ks < 4; ks++) {
            unsigned vf[4][4];
#pragma unroll
            for (int np = 0; np < 4; np++) {
                const int row = ks * 16 + (lane & 7) + ((lane >> 3) & 1) * 8;
                const int col = np * 16 + (lane >> 4) * 8;
                LDSM_X4_T(vf[np][0], vf[np][1], vf[np][2], vf[np][3],
                          cV + (row * 72 + col) * 2);
            }
#pragma unroll
            for (int mt = 0; mt < 2; mt++) {
                unsigned pf[4];
                pf[0] = pack_h2(sacc[mt][2 * ks][0],     sacc[mt][2 * ks][1]);
                pf[1] = pack_h2(sacc[mt][2 * ks][2],     sacc[mt][2 * ks][3]);
                pf[2] = pack_h2(sacc[mt][2 * ks + 1][0], sacc[mt][2 * ks + 1][1]);
                pf[3] = pack_h2(sacc[mt][2 * ks + 1][2], sacc[mt][2 * ks + 1][3]);
#pragma unroll
                for (int n = 0; n < 8; n++)
                    mma16(oacc[mt][n], pf,
                          vf[n >> 1][(n & 1) * 2], vf[n >> 1][(n & 1) * 2 + 1]);
            }
        }
    }

    // ---- epilogue ----
    const int b = bh >> 3;
    const int h = bh & 7;
#pragma unroll
    for (int mt = 0; mt < 2; mt++) {
        const float inv0 = 1.0f / lst[mt][0];
        const float inv1 = 1.0f / lst[mt][1];
        const int r0 = qbase + band + mt * 16 + g;
        __half* O0 = O + ((size_t)(b * NSEQ) + r0) * DIM + h * 64;
        __half* O1 = O + ((size_t)(b * NSEQ) + r0 + 8) * DIM + h * 64;
#pragma unroll
        for (int n = 0; n < 8; n++) {
            const int c = n * 8 + tg * 2;
            *(__half2*)&O0[c] = h2(oacc[mt][n][0] * inv0, oacc[mt][n][1] * inv0);
            *(__half2*)&O1[c] = h2(oacc[mt][n][2] * inv1, oacc[mt][n][3] * inv1);
        }
    }
}

// ---------------------------------------------------------------------------
// LayerNorm (over 1024) + exact GELU; fp32 in, fp16 out.
// ---------------------------------------------------------------------------
__device__ __forceinline__ float gelu_exact(float x) {
    return 0.5f * x * (1.0f + erff(x * 0.70710678118654752440f));
}

__global__ __launch_bounds__(256) void ln_gelu_kernel(
    const float* __restrict__ hc, __half* __restrict__ out16,
    const float* __restrict__ gam, const float* __restrict__ bet)
{
    const int row = blockIdx.x;
    const float* p = hc + (size_t)row * 1024;
    const int tid = threadIdx.x;

    float4 t = ((const float4*)p)[tid];
    float s  = t.x + t.y + t.z + t.w;
    float ss = t.x * t.x + t.y * t.y + t.z * t.z + t.w * t.w;

#pragma unroll
    for (int off = 16; off > 0; off >>= 1) {
        s  += __shfl_xor_sync(0xffffffffu, s,  off);
        ss += __shfl_xor_sync(0xffffffffu, ss, off);
    }

    __shared__ float rs[8], rss[8];
    __shared__ float s_mean, s_rstd;
    const int wid = tid >> 5, lane = tid & 31;
    if (lane == 0) { rs[wid] = s; rss[wid] = ss; }
    __syncthreads();
    if (tid == 0) {
        float S = 0.0f, SS = 0.0f;
#pragma unroll
        for (int w = 0; w < 8; w++) { S += rs[w]; SS += rss[w]; }
        const float mean = S * (1.0f / 1024.0f);
        const float var  = SS * (1.0f / 1024.0f) - mean * mean;
        s_mean = mean;
        s_rstd = rsqrtf(var + 1e-5f);
    }
    __syncthreads();

    const float mean = s_mean, rstd = s_rstd;
    const int col = tid * 4;
    float a = gelu_exact((t.x - mean) * rstd * gam[col]     + bet[col]);
    float b = gelu_exact((t.y - mean) * rstd * gam[col + 1] + bet[col + 1]);
    float c = gelu_exact((t.z - mean) * rstd * gam[col + 2] + bet[col + 2]);
    float d = gelu_exact((t.w - mean) * rstd * gam[col + 3] + bet[col + 3]);
    __half* q = out16 + (size_t)row * 1024 + col;
    *(__half2*)q       = h2(a, b);
    *(__half2*)(q + 2) = h2(c, d);
}

// ---------------------------------------------------------------------------
extern "C" void kernel_launch(void* const* d_in, const int* in_sizes, int n_in,
                              void* d_out, int out_size)
{
    const float* x      = (const float*)d_in[0];
    const float* freqs  = (const float*)d_in[1];
    const float* wqkv_w = (const float*)d_in[2];
    const float* wqkv_b = (const float*)d_in[3];
    const float* out_w  = (const float*)d_in[4];
    const float* out_b  = (const float*)d_in[5];
    const float* ffn1_w = (const float*)d_in[6];
    const float* ffn1_b = (const float*)d_in[7];
    const float* ln_g   = (const float*)d_in[8];
    const float* ln_b   = (const float*)d_in[9];
    const float* ffn2_w = (const float*)d_in[10];
    const float* ffn2_b = (const float*)d_in[11];
    float* out = (float*)d_out;

    float  *hcat;
    __half *qkvh, *xh, *wqkvh, *outwh, *ffn1h, *ffn2h;
    __half *qh, *kh, *vh, *atth, *msgh, *hcath;
    cudaGetSymbolAddress((void**)&hcat,  g_hcat);
    cudaGetSymbolAddress((void**)&qkvh,  g_qkvh);
    cudaGetSymbolAddress((void**)&xh,    g_xh);
    cudaGetSymbolAddress((void**)&wqkvh, g_wqkvh);
    cudaGetSymbolAddress((void**)&outwh, g_outwh);
    cudaGetSymbolAddress((void**)&ffn1h, g_ffn1h);
    cudaGetSymbolAddress((void**)&ffn2h, g_ffn2h);
    cudaGetSymbolAddress((void**)&qh,    g_qh);
    cudaGetSymbolAddress((void**)&kh,    g_kh);
    cudaGetSymbolAddress((void**)&vh,    g_vh);
    cudaGetSymbolAddress((void**)&atth,  g_atth);
    cudaGetSymbolAddress((void**)&msgh,  g_msgh);
    cudaGetSymbolAddress((void**)&hcath, g_hcath);

    cudaFuncSetAttribute(gemm_f16, cudaFuncAttributeMaxDynamicSharedMemorySize, GSMEM);
    cudaFuncSetAttribute(attn_f16, cudaFuncAttributeMaxDynamicSharedMemorySize, ATT_SMEM);

    // 0) fp32 -> fp16 converts (x + all weights)
    cvt16_kernel<<<ROWS * DIM / 1024, 256>>>(x,      xh);
    cvt16_kernel<<<512 * 1536 / 1024, 256>>>(wqkv_w, wqkvh);
    cvt16_kernel<<<512 * 512 / 1024,  256>>>(out_w,  outwh);
    cvt16_kernel<<<1024 * 1024 / 1024, 256>>>(ffn1_w, ffn1h);
    cvt16_kernel<<<1024 * 512 / 1024, 256>>>(ffn2_w, ffn2h);

    // 1) QKV projection -> fp16 qkv (RoPE input)
    gemm_f16<<<dim3(1536 / 128, ROWS / 256), 256, GSMEM>>>(
        xh, DIM, xh, DIM, 512, wqkvh, wqkv_b, nullptr, nullptr, qkvh, 1536, 512);

    // 2) RoPE + head transpose -> fp16 Q/K/V
    rope_kernel<<<ROWS, 256>>>(qkvh, freqs, qh, kh, vh);

    // 3) Attention -> fp16 att [B,N,D]
    attn_f16<<<dim3(NSEQ / 128, BATCH * NHEAD), 128, ATT_SMEM>>>(qh, kh, vh, atth);

    // 4) Out projection -> fp16 msg
    gemm_f16<<<dim3(512 / 128, ROWS / 256), 256, GSMEM>>>(
        atth, DIM, atth, DIM, 512, outwh, out_b, nullptr, nullptr, msgh, 512, 512);

    // 5) FFN1 over concat([x, msg]) -> fp32 hcat (LN input)
    gemm_f16<<<dim3(1024 / 128, ROWS / 256), 256, GSMEM>>>(
        xh, DIM, msgh, DIM, 512, ffn1h, ffn1_b, nullptr, hcat, nullptr, 1024, 1024);

    // 6) LayerNorm + GELU -> fp16
    ln_gelu_kernel<<<ROWS, 256>>>(hcat, hcath, ln_g, ln_b);

    // 7) FFN2 + residual x -> fp32 out
    gemm_f16<<<dim3(512 / 128, ROWS / 256), 256, GSMEM>>>(
        hcath, 2 * DIM, hcath, 2 * DIM, 1024, ffn2h, ffn2_b, x, out, nullptr, 512, 1024);
}

// round 12
// speedup vs baseline: 1.0094x; 1.0094x over previous
#include <cuda_runtime.h>
#include <cuda_fp16.h>
#include <cstdint>

#define BATCH 4
#define NSEQ  2048
#define DIM   512
#define NHEAD 8
#define HDIM  64
#define ROWS  (BATCH * NSEQ)   // 8192

// ---------------- scratch (static device globals; no allocations) ----------
__device__ float  g_hcat [ROWS * 2 * DIM];     // fp32 pre-LN
__device__ __half g_qkvh [ROWS * 3 * DIM];     // fp16 pre-RoPE
__device__ __half g_xh   [ROWS * DIM];
__device__ __half g_wqkvh[512 * 1536];
__device__ __half g_outwh[512 * 512];
__device__ __half g_ffn1h[1024 * 1024];        // full ffn1_w fp16 (W' B input)
__device__ __half g_comb [1024 * 1024];        // [W1top; out_w@W1bot] fp16
__device__ __half g_ffn2h[1024 * 512];
__device__ float  g_bias1[1024];               // ffn1_b + out_b @ W1bot
__device__ float  g_zero [1024];               // stays zero (module init)
__device__ __half g_qh   [ROWS * DIM];         // [BH][N][64], pre-scaled
__device__ __half g_kh   [ROWS * DIM];
__device__ __half g_vh   [ROWS * DIM];
__device__ __half g_atth [ROWS * DIM];         // [B,N,D] fp16
__device__ __half g_hcath[ROWS * 2 * DIM];

// ---------------------------------------------------------------------------
#define CP_ASYNC_CG(dst, src) \
    asm volatile("cp.async.cg.shared.global [%0], [%1], 16;" :: "r"(dst), "l"(src))
#define CP_COMMIT() asm volatile("cp.async.commit_group;")
#define CP_WAIT(n)  asm volatile("cp.async.wait_group %0;" :: "n"(n))

__device__ __forceinline__ unsigned smem_u32(const void* p) {
    unsigned a;
    asm("{ .reg .u64 t; cvta.to.shared.u64 t, %1; cvt.u32.u64 %0, t; }"
        : "=r"(a) : "l"(p));
    return a;
}

#define LDSM_X4(r0, r1, r2, r3, addr) \
    asm volatile("ldmatrix.sync.aligned.m8n8.x4.shared.b16 {%0,%1,%2,%3}, [%4];" \
                 : "=r"(r0), "=r"(r1), "=r"(r2), "=r"(r3) : "r"(addr))
#define LDSM_X4_T(r0, r1, r2, r3, addr) \
    asm volatile("ldmatrix.sync.aligned.m8n8.x4.trans.shared.b16 {%0,%1,%2,%3}, [%4];" \
                 : "=r"(r0), "=r"(r1), "=r"(r2), "=r"(r3) : "r"(addr))

__device__ __forceinline__ void mma16(float* d, const unsigned* a,
                                      unsigned b0, unsigned b1) {
    asm volatile(
        "mma.sync.aligned.m16n8k16.row.col.f32.f16.f16.f32 "
        "{%0,%1,%2,%3},{%4,%5,%6,%7},{%8,%9},{%0,%1,%2,%3};\n"
        : "+f"(d[0]), "+f"(d[1]), "+f"(d[2]), "+f"(d[3])
        : "r"(a[0]), "r"(a[1]), "r"(a[2]), "r"(a[3]), "r"(b0), "r"(b1));
}

__device__ __forceinline__ __half2 h2(float a, float b) {
    return __floats2half2_rn(a, b);
}

__device__ __forceinline__ unsigned pack_h2(float a, float b) {
    __half2 h = __floats2half2_rn(a, b);
    return *(unsigned*)&h;
}

// ---------------------------------------------------------------------------
// fp32 -> fp16 convert (n % 1024 == 0).
// ---------------------------------------------------------------------------
__global__ __launch_bounds__(256) void cvt16_kernel(
    const float* __restrict__ in, __half* __restrict__ out)
{
    const int i = (blockIdx.x * 256 + threadIdx.x) * 4;
    float4 v = *(const float4*)(in + i);
    *(__half2*)(out + i)     = h2(v.x, v.y);
    *(__half2*)(out + i + 2) = h2(v.z, v.w);
}

// ---------------------------------------------------------------------------
// Folded FFN1 bias: b'[n] = ffn1_b[n] + sum_k out_b[k] * ffn1_w[512+k][n].
// Grid 4 x 256 threads (one thread per n).
// ---------------------------------------------------------------------------
__global__ __launch_bounds__(256) void bias1_kernel(
    const float* __restrict__ ffn1_b, const float* __restrict__ out_b,
    const float* __restrict__ ffn1_w, float* __restrict__ bias1)
{
    const int n = blockIdx.x * 256 + threadIdx.x;   // 0..1023
    float acc = ffn1_b[n];
    const float* wrow = ffn1_w + (size_t)512 * 1024 + n;
    for (int k = 0; k < 512; k++)
        acc = fmaf(out_b[k], wrow[(size_t)k * 1024], acc);
    bias1[n] = acc;
}

// ---------------------------------------------------------------------------
// fp16 GEMM (R10 config): 128x128 CTA tile, 8 warps (4m x 2n) of 32x64,
// BK=32, 2-stage cp.async pipeline, static smem 37.9 KB -> 2 CTAs/SM.
// A fp16 split at `ksplit` (A0/A1), B fp16 [K][N].  Out: C32 and/or C16.
// ---------------------------------------------------------------------------
__global__ __launch_bounds__(256) void gemm_f16(
    const __half* __restrict__ A0, int lda0,
    const __half* __restrict__ A1, int lda1, int ksplit,
    const __half* __restrict__ B,
    const float* __restrict__ bias,
    const float* __restrict__ resid,
    float* __restrict__ C32, __half* __restrict__ C16, int N, int K)
{
    __shared__ __half sA[2][128][40];
    __shared__ __half sB[2][32][136];

    const int tid  = threadIdx.x;
    const int warp = tid >> 5;
    const int lane = tid & 31;
    const int g    = lane >> 2;
    const int tg   = lane & 3;
    const int wm   = (warp >> 1) * 32;
    const int wn   = (warp & 1) * 64;

    const int bm = blockIdx.y * 128;
    const int bn = blockIdx.x * 128;

    const unsigned uA = smem_u32(&sA[0][0][0]);
    const unsigned uB = smem_u32(&sB[0][0][0]);

    float acc[2][8][4];
#pragma unroll
    for (int mt = 0; mt < 2; mt++)
#pragma unroll
        for (int nt = 0; nt < 8; nt++)
#pragma unroll
            for (int c = 0; c < 4; c++) acc[mt][nt][c] = 0.0f;

    const int NT = K >> 5;

    auto prefetch = [&](int t, int s) {
        const int k0 = t << 5;
#pragma unroll
        for (int i = 0; i < 2; i++) {
            const int idx = i * 256 + tid;       // 0..511
            const int r   = idx >> 2;            // 0..127
            const int c8  = (idx & 3) << 3;      // 0,8,16,24
            const __half* ap = (k0 < ksplit)
                ? A0 + (size_t)(bm + r) * lda0 + k0 + c8
                : A1 + (size_t)(bm + r) * lda1 + (k0 - ksplit) + c8;
            CP_ASYNC_CG(uA + (s * 128 * 40 + r * 40 + c8) * 2, ap);
        }
#pragma unroll
        for (int i = 0; i < 2; i++) {
            const int idx = i * 256 + tid;       // 0..511
            const int r   = idx >> 4;            // 0..31
            const int c8  = (idx & 15) << 3;     // 0..120
            CP_ASYNC_CG(uB + (s * 32 * 136 + r * 136 + c8) * 2,
                        B + (size_t)(k0 + r) * N + bn + c8);
        }
    };

    prefetch(0, 0);
    CP_COMMIT();

    for (int t = 0; t < NT; t++) {
        __syncthreads();
        if (t + 1 < NT) { prefetch(t + 1, (t + 1) & 1); CP_COMMIT(); CP_WAIT(1); }
        else            { CP_WAIT(0); }
        __syncthreads();

        const unsigned aBase = uA + ((t & 1) * 128 * 40) * 2;
        const unsigned bBase = uB + ((t & 1) * 32 * 136) * 2;

#pragma unroll
        for (int ks = 0; ks < 2; ks++) {
            unsigned af[2][4];
#pragma unroll
            for (int mt = 0; mt < 2; mt++) {
                const int row = wm + mt * 16 + (lane & 7) + ((lane >> 3) & 1) * 8;
                const int col = ks * 16 + (lane >> 4) * 8;
                LDSM_X4(af[mt][0], af[mt][1], af[mt][2], af[mt][3],
                        aBase + (row * 40 + col) * 2);
            }
            unsigned bf[4][4];
#pragma unroll
            for (int np = 0; np < 4; np++) {
                const int row = ks * 16 + (lane & 7) + ((lane >> 3) & 1) * 8;
                const int col = wn + np * 16 + (lane >> 4) * 8;
                LDSM_X4_T(bf[np][0], bf[np][1], bf[np][2], bf[np][3],
                          bBase + (row * 136 + col) * 2);
            }
#pragma unroll
            for (int mt = 0; mt < 2; mt++)
#pragma unroll
                for (int nt = 0; nt < 8; nt++)
                    mma16(acc[mt][nt], af[mt],
                          bf[nt >> 1][(nt & 1) * 2], bf[nt >> 1][(nt & 1) * 2 + 1]);
        }
    }

    // ---- epilogue ----
#pragma unroll
    for (int mt = 0; mt < 2; mt++) {
        const int r0 = bm + wm + mt * 16 + g;
#pragma unroll
        for (int nt = 0; nt < 8; nt++) {
            const int col = bn + wn + nt * 8 + tg * 2;
            float2 bb = *(const float2*)&bias[col];
            float2 v0, v1;
            v0.x = acc[mt][nt][0] + bb.x;
            v0.y = acc[mt][nt][1] + bb.y;
            v1.x = acc[mt][nt][2] + bb.x;
            v1.y = acc[mt][nt][3] + bb.y;
            const size_t o0 = (size_t)r0 * N + col;
            const size_t o1 = (size_t)(r0 + 8) * N + col;
            if (resid) {
                float2 rr0 = *(const float2*)&resid[o0];
                float2 rr1 = *(const float2*)&resid[o1];
                v0.x += rr0.x; v0.y += rr0.y;
                v1.x += rr1.x; v1.y += rr1.y;
            }
            if (C32) {
                *(float2*)&C32[o0] = v0;
                *(float2*)&C32[o1] = v1;
            }
            if (C16) {
                *(__half2*)&C16[o0] = h2(v0.x, v0.y);
                *(__half2*)&C16[o1] = h2(v1.x, v1.y);
            }
        }
    }
}

// ---------------------------------------------------------------------------
// RoPE + split + head transpose; fp16 in (qkv), fp16 out, math in fp32.
// ---------------------------------------------------------------------------
__global__ __launch_bounds__(256) void rope_kernel(
    const __half* __restrict__ qkv, const float* __restrict__ freqs,
    __half* __restrict__ Q, __half* __restrict__ K, __half* __restrict__ V)
{
    const int bn = blockIdx.x;
    const int b  = bn >> 11;
    const int h  = threadIdx.x >> 5;
    const int i  = threadIdx.x & 31;
    const int n  = bn & 2047;

    const float f = freqs[(size_t)bn * 32 + i];
    const float c = cosf(f), s = sinf(f);

    const __half* base = qkv + (size_t)bn * 1536;
    const int e = h * 64 + 2 * i;

    const float2 q2 = __half22float2(*(const __half2*)(base + e));
    const float2 k2 = __half22float2(*(const __half2*)(base + 512 + e));
    const __half2 v2 = *(const __half2*)(base + 1024 + e);

    const size_t oidx = (((size_t)(b * NHEAD + h)) * NSEQ + n) * 64 + 2 * i;
    *(__half2*)(Q + oidx) = h2((q2.x * c - q2.y * s) * 0.125f,
                               (q2.x * s + q2.y * c) * 0.125f);
    *(__half2*)(K + oidx) = h2(k2.x * c - k2.y * s, k2.x * s + k2.y * c);
    *(__half2*)(V + oidx) = v2;
}

// ---------------------------------------------------------------------------
// Flash attention, fp16 mma (m16n8k16), FA2 register path (unchanged R10).
// ---------------------------------------------------------------------------
#define ATT_SMEM ((128 * 72 + 2 * 64 * 72 + 2 * 64 * 72) * 2)

__global__ __launch_bounds__(128) void attn_f16(
    const __half* __restrict__ Qg_, const __half* __restrict__ Kg_,
    const __half* __restrict__ Vg_, __half* __restrict__ O)
{
    extern __shared__ __half hsm[];
    const unsigned uQ = smem_u32(hsm);
    const unsigned uK = uQ + 128 * 72 * 2;
    const unsigned uV = uK + 2 * 64 * 72 * 2;

    const int tid  = threadIdx.x;
    const int warp = tid >> 5;
    const int lane = tid & 31;
    const int g    = lane >> 2;
    const int tg   = lane & 3;
    const int band = warp * 32;

    const int bh    = blockIdx.y;
    const int qbase = blockIdx.x * 128;

    const __half* Qg = Qg_ + ((size_t)bh * NSEQ + qbase) * 64;
    const __half* Kg = Kg_ + (size_t)bh * NSEQ * 64;
    const __half* Vg = Vg_ + (size_t)bh * NSEQ * 64;

    auto prefetchKV = [&](int tile, int s) {
#pragma unroll
        for (int i = 0; i < 4; i++) {
            const int idx = i * 128 + tid;     // 0..511
            const int r   = idx >> 3;          // 0..63
            const int c8  = (idx & 7) << 3;
            const size_t off = (size_t)(tile * 64 + r) * 64 + c8;
            CP_ASYNC_CG(uK + (s * 64 * 72 + r * 72 + c8) * 2, Kg + off);
            CP_ASYNC_CG(uV + (s * 64 * 72 + r * 72 + c8) * 2, Vg + off);
        }
    };

#pragma unroll
    for (int i = 0; i < 8; i++) {
        const int idx = i * 128 + tid;
        const int r   = idx >> 3;
        const int c8  = (idx & 7) << 3;
        CP_ASYNC_CG(uQ + (r * 72 + c8) * 2, Qg + (size_t)r * 64 + c8);
    }
    prefetchKV(0, 0);
    CP_COMMIT();

    unsigned qf[2][4][4];
    float oacc[2][8][4];
#pragma unroll
    for (int mt = 0; mt < 2; mt++)
#pragma unroll
        for (int n = 0; n < 8; n++)
#pragma unroll
            for (int c = 0; c < 4; c++) oacc[mt][n][c] = 0.0f;
    float mst[2][2] = {{-1e30f, -1e30f}, {-1e30f, -1e30f}};
    float lst[2][2] = {{0.0f, 0.0f}, {0.0f, 0.0f}};

    const int NT = NSEQ / 64;
    for (int t = 0; t < NT; t++) {
        __syncthreads();
        if (t + 1 < NT) { prefetchKV(t + 1, (t + 1) & 1); CP_COMMIT(); CP_WAIT(1); }
        else            { CP_WAIT(0); }
        __syncthreads();

        if (t == 0) {
#pragma unroll
            for (int mt = 0; mt < 2; mt++)
#pragma unroll
                for (int ks = 0; ks < 4; ks++) {
                    const int row = band + mt * 16 + (lane & 7) + ((lane >> 3) & 1) * 8;
                    const int col = ks * 16 + (lane >> 4) * 8;
                    LDSM_X4(qf[mt][ks][0], qf[mt][ks][1], qf[mt][ks][2], qf[mt][ks][3],
                            uQ + (row * 72 + col) * 2);
                }
        }

        const unsigned cK = uK + ((t & 1) * 64 * 72) * 2;
        const unsigned cV = uV + ((t & 1) * 64 * 72) * 2;

        // ---- S = Q @ K^T ----
        float sacc[2][8][4];
#pragma unroll
        for (int mt = 0; mt < 2; mt++)
#pragma unroll
            for (int n = 0; n < 8; n++)
#pragma unroll
                for (int c = 0; c < 4; c++) sacc[mt][n][c] = 0.0f;

#pragma unroll
        for (int ks = 0; ks < 4; ks++) {
            unsigned kf[4][4];
#pragma unroll
            for (int kp = 0; kp < 4; kp++) {
                const int row = kp * 16 + (lane & 7) + (lane >> 4) * 8;
                const int col = ks * 16 + ((lane >> 3) & 1) * 8;
                LDSM_X4(kf[kp][0], kf[kp][1], kf[kp][2], kf[kp][3],
                        cK + (row * 72 + col) * 2);
            }
#pragma unroll
            for (int mt = 0; mt < 2; mt++)
#pragma unroll
                for (int n = 0; n < 8; n++)
                    mma16(sacc[mt][n], qf[mt][ks],
                          kf[n >> 1][(n & 1) * 2], kf[n >> 1][(n & 1) * 2 + 1]);
        }

        // ---- online softmax ----
#pragma unroll
        for (int mt = 0; mt < 2; mt++) {
            float r0 = -1e30f, r1 = -1e30f;
#pragma unroll
            for (int n = 0; n < 8; n++) {
                r0 = fmaxf(r0, fmaxf(sacc[mt][n][0], sacc[mt][n][1]));
                r1 = fmaxf(r1, fmaxf(sacc[mt][n][2], sacc[mt][n][3]));
            }
            r0 = fmaxf(r0, __shfl_xor_sync(0xffffffffu, r0, 1));
            r0 = fmaxf(r0, __shfl_xor_sync(0xffffffffu, r0, 2));
            r1 = fmaxf(r1, __shfl_xor_sync(0xffffffffu, r1, 1));
            r1 = fmaxf(r1, __shfl_xor_sync(0xffffffffu, r1, 2));

            const float mn0 = fmaxf(mst[mt][0], r0);
            const float mn1 = fmaxf(mst[mt][1], r1);
            const float c0 = __expf(mst[mt][0] - mn0);
            const float c1 = __expf(mst[mt][1] - mn1);

            float s0 = 0.0f, s1 = 0.0f;
#pragma unroll
            for (int n = 0; n < 8; n++) {
                sacc[mt][n][0] = __expf(sacc[mt][n][0] - mn0);
                sacc[mt][n][1] = __expf(sacc[mt][n][1] - mn0);
                sacc[mt][n][2] = __expf(sacc[mt][n][2] - mn1);
                sacc[mt][n][3] = __expf(sacc[mt][n][3] - mn1);
                s0 += sacc[mt][n][0] + sacc[mt][n][1];
                s1 += sacc[mt][n][2] + sacc[mt][n][3];
            }
            s0 += __shfl_xor_sync(0xffffffffu, s0, 1);
            s0 += __shfl_xor_sync(0xffffffffu, s0, 2);
            s1 += __shfl_xor_sync(0xffffffffu, s1, 1);
            s1 += __shfl_xor_sync(0xffffffffu, s1, 2);

            lst[mt][0] = lst[mt][0] * c0 + s0;
            lst[mt][1] = lst[mt][1] * c1 + s1;
#pragma unroll
            for (int n = 0; n < 8; n++) {
                oacc[mt][n][0] *= c0;  oacc[mt][n][1] *= c0;
                oacc[mt][n][2] *= c1;  oacc[mt][n][3] *= c1;
            }
            mst[mt][0] = mn0;  mst[mt][1] = mn1;
        }

        // ---- O += P @ V ----
#pragma unroll
        for (int ks = 0; ks < 4; ks++) {
            unsigned vf[4][4];
#pragma unroll
            for (int np = 0; np < 4; np++) {
                const int row = ks * 16 + (lane & 7) + ((lane >> 3) & 1) * 8;
                const int col = np * 16 + (lane >> 4) * 8;
                LDSM_X4_T(vf[np][0], vf[np][1], vf[np][2], vf[np][3],
                          cV + (row * 72 + col) * 2);
            }
#pragma unroll
            for (int mt = 0; mt < 2; mt++) {
                unsigned pf[4];
                pf[0] = pack_h2(sacc[mt][2 * ks][0],     sacc[mt][2 * ks][1]);
                pf[1] = pack_h2(sacc[mt][2 * ks][2],     sacc[mt][2 * ks][3]);
                pf[2] = pack_h2(sacc[mt][2 * ks + 1][0], sacc[mt][2 * ks + 1][1]);
                pf[3] = pack_h2(sacc[mt][2 * ks + 1][2], sacc[mt][2 * ks + 1][3]);
#pragma unroll
                for (int n = 0; n < 8; n++)
                    mma16(oacc[mt][n], pf,
                          vf[n >> 1][(n & 1) * 2], vf[n >> 1][(n & 1) * 2 + 1]);
            }
        }
    }

    // ---- epilogue ----
    const int b = bh >> 3;
    const int h = bh & 7;
#pragma unroll
    for (int mt = 0; mt < 2; mt++) {
        const float inv0 = 1.0f / lst[mt][0];
        const float inv1 = 1.0f / lst[mt][1];
        const int r0 = qbase + band + mt * 16 + g;
        __half* O0 = O + ((size_t)(b * NSEQ) + r0) * DIM + h * 64;
        __half* O1 = O + ((size_t)(b * NSEQ) + r0 + 8) * DIM + h * 64;
#pragma unroll
        for (int n = 0; n < 8; n++) {
            const int c = n * 8 + tg * 2;
            *(__half2*)&O0[c] = h2(oacc[mt][n][0] * inv0, oacc[mt][n][1] * inv0);
            *(__half2*)&O1[c] = h2(oacc[mt][n][2] * inv1, oacc[mt][n][3] * inv1);
        }
    }
}

// ---------------------------------------------------------------------------
// LayerNorm (over 1024) + exact GELU; fp32 in, fp16 out.
// ---------------------------------------------------------------------------
__device__ __forceinline__ float gelu_exact(float x) {
    return 0.5f * x * (1.0f + erff(x * 0.70710678118654752440f));
}

__global__ __launch_bounds__(256) void ln_gelu_kernel(
    const float* __restrict__ hc, __half* __restrict__ out16,
    const float* __restrict__ gam, const float* __restrict__ bet)
{
    const int row = blockIdx.x;
    const float* p = hc + (size_t)row * 1024;
    const int tid = threadIdx.x;

    float4 t = ((const float4*)p)[tid];
    float s  = t.x + t.y + t.z + t.w;
    float ss = t.x * t.x + t.y * t.y + t.z * t.z + t.w * t.w;

#pragma unroll
    for (int off = 16; off > 0; off >>= 1) {
        s  += __shfl_xor_sync(0xffffffffu, s,  off);
        ss += __shfl_xor_sync(0xffffffffu, ss, off);
    }

    __shared__ float rs[8], rss[8];
    __shared__ float s_mean, s_rstd;
    const int wid = tid >> 5, lane = tid & 31;
    if (lane == 0) { rs[wid] = s; rss[wid] = ss; }
    __syncthreads();
    if (tid == 0) {
        float S = 0.0f, SS = 0.0f;
#pragma unroll
        for (int w = 0; w < 8; w++) { S += rs[w]; SS += rss[w]; }
        const float mean = S * (1.0f / 1024.0f);
        const float var  = SS * (1.0f / 1024.0f) - mean * mean;
        s_mean = mean;
        s_rstd = rsqrtf(var + 1e-5f);
    }
    __syncthreads();

    const float mean = s_mean, rstd = s_rstd;
    const int col = tid * 4;
    float a = gelu_exact((t.x - mean) * rstd * gam[col]     + bet[col]);
    float b = gelu_exact((t.y - mean) * rstd * gam[col + 1] + bet[col + 1]);
    float c = gelu_exact((t.z - mean) * rstd * gam[col + 2] + bet[col + 2]);
    float d = gelu_exact((t.w - mean) * rstd * gam[col + 3] + bet[col + 3]);
    __half* q = out16 + (size_t)row * 1024 + col;
    *(__half2*)q       = h2(a, b);
    *(__half2*)(q + 2) = h2(c, d);
}

// ---------------------------------------------------------------------------
extern "C" void kernel_launch(void* const* d_in, const int* in_sizes, int n_in,
                              void* d_out, int out_size)
{
    const float* x      = (const float*)d_in[0];
    const float* freqs  = (const float*)d_in[1];
    const float* wqkv_w = (const float*)d_in[2];
    const float* wqkv_b = (const float*)d_in[3];
    const float* out_w  = (const float*)d_in[4];
    const float* out_b  = (const float*)d_in[5];
    const float* ffn1_w = (const float*)d_in[6];
    const float* ffn1_b = (const float*)d_in[7];
    const float* ln_g   = (const float*)d_in[8];
    const float* ln_b   = (const float*)d_in[9];
    const float* ffn2_w = (const float*)d_in[10];
    const float* ffn2_b = (const float*)d_in[11];
    float* out = (float*)d_out;

    float  *hcat, *bias1, *zero;
    __half *qkvh, *xh, *wqkvh, *outwh, *ffn1h, *comb, *ffn2h;
    __half *qh, *kh, *vh, *atth, *hcath;
    cudaGetSymbolAddress((void**)&hcat,  g_hcat);
    cudaGetSymbolAddress((void**)&bias1, g_bias1);
    cudaGetSymbolAddress((void**)&zero,  g_zero);
    cudaGetSymbolAddress((void**)&qkvh,  g_qkvh);
    cudaGetSymbolAddress((void**)&xh,    g_xh);
    cudaGetSymbolAddress((void**)&wqkvh, g_wqkvh);
    cudaGetSymbolAddress((void**)&outwh, g_outwh);
    cudaGetSymbolAddress((void**)&ffn1h, g_ffn1h);
    cudaGetSymbolAddress((void**)&comb,  g_comb);
    cudaGetSymbolAddress((void**)&ffn2h, g_ffn2h);
    cudaGetSymbolAddress((void**)&qh,    g_qh);
    cudaGetSymbolAddress((void**)&kh,    g_kh);
    cudaGetSymbolAddress((void**)&vh,    g_vh);
    cudaGetSymbolAddress((void**)&atth,  g_atth);
    cudaGetSymbolAddress((void**)&hcath, g_hcath);

    cudaFuncSetAttribute(attn_f16, cudaFuncAttributeMaxDynamicSharedMemorySize, ATT_SMEM);

    // 0) fp32 -> fp16 converts
    cvt16_kernel<<<ROWS * DIM / 1024, 256>>>(x,      xh);
    cvt16_kernel<<<512 * 1536 / 1024, 256>>>(wqkv_w, wqkvh);
    cvt16_kernel<<<512 * 512 / 1024,  256>>>(out_w,  outwh);
    cvt16_kernel<<<1024 * 1024 / 1024, 256>>>(ffn1_w, ffn1h);
    cvt16_kernel<<<512 * 1024 / 1024, 256>>>(ffn1_w, comb);   // W1top -> comb rows 0..511
    cvt16_kernel<<<1024 * 512 / 1024, 256>>>(ffn2_w, ffn2h);

    // 0b) Folded FFN1 bias:  bias1 = ffn1_b + out_b @ W1bot
    bias1_kernel<<<4, 256>>>(ffn1_b, out_b, ffn1_w, bias1);

    // 0c) W' = out_w @ W1bot  ->  comb rows 512..1023  (M=512,K=512,N=1024)
    gemm_f16<<<dim3(1024 / 128, 512 / 128), 256>>>(
        outwh, 512, outwh, 512, 512, ffn1h + (size_t)512 * 1024,
        zero, nullptr, nullptr, comb + (size_t)512 * 1024, 1024, 512);

    // 1) QKV projection -> fp16 qkv (RoPE input)
    gemm_f16<<<dim3(1536 / 128, ROWS / 128), 256>>>(
        xh, DIM, xh, DIM, 512, wqkvh, wqkv_b, nullptr, nullptr, qkvh, 1536, 512);

    // 2) RoPE + head transpose -> fp16 Q/K/V
    rope_kernel<<<ROWS, 256>>>(qkvh, freqs, qh, kh, vh);

    // 3) Attention -> fp16 att [B,N,D]
    attn_f16<<<dim3(NSEQ / 128, BATCH * NHEAD), 128, ATT_SMEM>>>(qh, kh, vh, atth);

    // 4) Fused out-proj + FFN1:  hcat = x@W1top + att@W' + bias1  (fp32 out)
    gemm_f16<<<dim3(1024 / 128, ROWS / 128), 256>>>(
        xh, DIM, atth, DIM, 512, comb, bias1, nullptr, hcat, nullptr, 1024, 1024);

    // 5) LayerNorm + GELU -> fp16
    ln_gelu_kernel<<<ROWS, 256>>>(hcat, hcath, ln_g, ln_b);

    // 6) FFN2 + residual x -> fp32 out
    gemm_f16<<<dim3(512 / 128, ROWS / 128), 256>>>(
        hcath, 2 * DIM, hcath, 2 * DIM, 1024, ffn2h, ffn2_b, x, out, nullptr, 512, 1024);
}

// round 13
// speedup vs baseline: 1.1130x; 1.1026x over previous
#include <cuda_runtime.h>
#include <cuda_fp16.h>
#include <cstdint>

#define BATCH 4
#define NSEQ  2048
#define DIM   512
#define NHEAD 8
#define HDIM  64
#define ROWS  (BATCH * NSEQ)   // 8192

// ---------------- scratch (static device globals; no allocations) ----------
__device__ __half g_qkvh [ROWS * 3 * DIM];     // fp16 pre-RoPE
__device__ __half g_xh   [ROWS * DIM];
__device__ __half g_wqkvh[512 * 1536];
__device__ __half g_outwh[512 * 512];
__device__ __half g_ffn1h[1024 * 1024];
__device__ __half g_ffn2h[1024 * 512];
__device__ __half g_qh   [ROWS * DIM];         // [BH][N][64], pre-scaled
__device__ __half g_kh   [ROWS * DIM];
__device__ __half g_vh   [ROWS * DIM];
__device__ __half g_atth [ROWS * DIM];         // [B,N,D] fp16
__device__ __half g_msgh [ROWS * DIM];
__device__ __half g_hcath[ROWS * 2 * DIM];

// ---------------------------------------------------------------------------
#define CP_ASYNC_CG(dst, src) \
    asm volatile("cp.async.cg.shared.global [%0], [%1], 16;" :: "r"(dst), "l"(src))
#define CP_COMMIT() asm volatile("cp.async.commit_group;")
#define CP_WAIT(n)  asm volatile("cp.async.wait_group %0;" :: "n"(n))

__device__ __forceinline__ unsigned smem_u32(const void* p) {
    unsigned a;
    asm("{ .reg .u64 t; cvta.to.shared.u64 t, %1; cvt.u32.u64 %0, t; }"
        : "=r"(a) : "l"(p));
    return a;
}

#define LDSM_X4(r0, r1, r2, r3, addr) \
    asm volatile("ldmatrix.sync.aligned.m8n8.x4.shared.b16 {%0,%1,%2,%3}, [%4];" \
                 : "=r"(r0), "=r"(r1), "=r"(r2), "=r"(r3) : "r"(addr))
#define LDSM_X4_T(r0, r1, r2, r3, addr) \
    asm volatile("ldmatrix.sync.aligned.m8n8.x4.trans.shared.b16 {%0,%1,%2,%3}, [%4];" \
                 : "=r"(r0), "=r"(r1), "=r"(r2), "=r"(r3) : "r"(addr))

__device__ __forceinline__ void mma16(float* d, const unsigned* a,
                                      unsigned b0, unsigned b1) {
    asm volatile(
        "mma.sync.aligned.m16n8k16.row.col.f32.f16.f16.f32 "
        "{%0,%1,%2,%3},{%4,%5,%6,%7},{%8,%9},{%0,%1,%2,%3};\n"
        : "+f"(d[0]), "+f"(d[1]), "+f"(d[2]), "+f"(d[3])
        : "r"(a[0]), "r"(a[1]), "r"(a[2]), "r"(a[3]), "r"(b0), "r"(b1));
}

__device__ __forceinline__ __half2 h2(float a, float b) {
    return __floats2half2_rn(a, b);
}

__device__ __forceinline__ unsigned pack_h2(float a, float b) {
    __half2 h = __floats2half2_rn(a, b);
    return *(unsigned*)&h;
}

// ---------------------------------------------------------------------------
// One-shot fused fp32->fp16 convert of x + all 4 weight tensors.
// Segment boundaries in float4 units (compile-time).
// ---------------------------------------------------------------------------
#define SEG_X   (ROWS * DIM / 4)           // 1048576
#define SEG_W0  (SEG_X  + 512 * 1536 / 4)  // +196608
#define SEG_W1  (SEG_W0 + 512 * 512 / 4)   // +65536
#define SEG_W2  (SEG_W1 + 1024 * 1024 / 4) // +262144
#define SEG_W3  (SEG_W2 + 1024 * 512 / 4)  // +131072 -> 1703936 total

__global__ __launch_bounds__(256) void cvt_all_kernel(
    const float* __restrict__ x,      const float* __restrict__ wqkv,
    const float* __restrict__ outw,   const float* __restrict__ ffn1,
    const float* __restrict__ ffn2,
    __half* __restrict__ xh,    __half* __restrict__ wqkvh,
    __half* __restrict__ outwh, __half* __restrict__ ffn1h,
    __half* __restrict__ ffn2h)
{
    const int v = blockIdx.x * 256 + threadIdx.x;   // float4 index
    const float* src;  __half* dst;  int base;
    if      (v < SEG_X)  { src = x;    dst = xh;    base = 0; }
    else if (v < SEG_W0) { src = wqkv; dst = wqkvh; base = SEG_X; }
    else if (v < SEG_W1) { src = outw; dst = outwh; base = SEG_W0; }
    else if (v < SEG_W2) { src = ffn1; dst = ffn1h; base = SEG_W1; }
    else                 { src = ffn2; dst = ffn2h; base = SEG_W2; }
    const int i = (v - base) * 4;
    float4 t = *(const float4*)(src + i);
    *(__half2*)(dst + i)     = h2(t.x, t.y);
    *(__half2*)(dst + i + 2) = h2(t.z, t.w);
}

// ---------------------------------------------------------------------------
// fp16 GEMM: 128x128 CTA tile, 8 warps (4m x 2n) of 32x64, BK=32,
// 3-stage cp.async pipeline, dynamic smem 56832 B -> 2 CTAs/SM.
// A fp16 split at `ksplit` (A0/A1), B fp16 [K][N].  Out: C32 and/or C16.
// ---------------------------------------------------------------------------
#define GST    (128 * 40 + 32 * 136)   // halves per stage (9472)
#define GSMEM  (3 * GST * 2)           // 56832 B

__global__ __launch_bounds__(256) void gemm_f16(
    const __half* __restrict__ A0, int lda0,
    const __half* __restrict__ A1, int lda1, int ksplit,
    const __half* __restrict__ B,
    const float* __restrict__ bias,
    const float* __restrict__ resid,
    float* __restrict__ C32, __half* __restrict__ C16, int N, int K)
{
    extern __shared__ __half gsm[];
    const unsigned uS = smem_u32(gsm);

    const int tid  = threadIdx.x;
    const int warp = tid >> 5;
    const int lane = tid & 31;
    const int g    = lane >> 2;
    const int tg   = lane & 3;
    const int wm   = (warp >> 1) * 32;
    const int wn   = (warp & 1) * 64;

    const int bm = blockIdx.y * 128;
    const int bn = blockIdx.x * 128;

    float acc[2][8][4];
#pragma unroll
    for (int mt = 0; mt < 2; mt++)
#pragma unroll
        for (int nt = 0; nt < 8; nt++)
#pragma unroll
            for (int c = 0; c < 4; c++) acc[mt][nt][c] = 0.0f;

    const int NT = K >> 5;

    auto prefetch = [&](int t, int s) {
        const int k0 = t << 5;
        const unsigned uA = uS + (s * GST) * 2;
        const unsigned uB = uA + (128 * 40) * 2;
#pragma unroll
        for (int i = 0; i < 2; i++) {
            const int idx = i * 256 + tid;       // 0..511
            const int r   = idx >> 2;            // 0..127
            const int c8  = (idx & 3) << 3;      // 0,8,16,24
            const __half* ap = (k0 < ksplit)
                ? A0 + (size_t)(bm + r) * lda0 + k0 + c8
                : A1 + (size_t)(bm + r) * lda1 + (k0 - ksplit) + c8;
            CP_ASYNC_CG(uA + (r * 40 + c8) * 2, ap);
        }
#pragma unroll
        for (int i = 0; i < 2; i++) {
            const int idx = i * 256 + tid;       // 0..511
            const int r   = idx >> 4;            // 0..31
            const int c8  = (idx & 15) << 3;     // 0..120
            CP_ASYNC_CG(uB + (r * 136 + c8) * 2,
                        B + (size_t)(k0 + r) * N + bn + c8);
        }
    };

    prefetch(0, 0); CP_COMMIT();
    prefetch(1, 1); CP_COMMIT();

    for (int t = 0; t < NT; t++) {
        CP_WAIT(1);          // tile t's group complete (1 newer outstanding)
        __syncthreads();     // all warps done with iter t-1 (refill target)
        if (t + 2 < NT) prefetch(t + 2, (t + 2) % 3);
        CP_COMMIT();         // possibly empty — keeps group accounting fixed

        const int s = t % 3;
        const unsigned aBase = uS + (s * GST) * 2;
        const unsigned bBase = aBase + (128 * 40) * 2;

#pragma unroll
        for (int ks = 0; ks < 2; ks++) {
            unsigned af[2][4];
#pragma unroll
            for (int mt = 0; mt < 2; mt++) {
                const int row = wm + mt * 16 + (lane & 7) + ((lane >> 3) & 1) * 8;
                const int col = ks * 16 + (lane >> 4) * 8;
                LDSM_X4(af[mt][0], af[mt][1], af[mt][2], af[mt][3],
                        aBase + (row * 40 + col) * 2);
            }
            unsigned bf[4][4];
#pragma unroll
            for (int np = 0; np < 4; np++) {
                const int row = ks * 16 + (lane & 7) + ((lane >> 3) & 1) * 8;
                const int col = wn + np * 16 + (lane >> 4) * 8;
                LDSM_X4_T(bf[np][0], bf[np][1], bf[np][2], bf[np][3],
                          bBase + (row * 136 + col) * 2);
            }
#pragma unroll
            for (int mt = 0; mt < 2; mt++)
#pragma unroll
                for (int nt = 0; nt < 8; nt++)
                    mma16(acc[mt][nt], af[mt],
                          bf[nt >> 1][(nt & 1) * 2], bf[nt >> 1][(nt & 1) * 2 + 1]);
        }
    }

    // ---- epilogue ----
#pragma unroll
    for (int mt = 0; mt < 2; mt++) {
        const int r0 = bm + wm + mt * 16 + g;
#pragma unroll
        for (int nt = 0; nt < 8; nt++) {
            const int col = bn + wn + nt * 8 + tg * 2;
            float2 bb = *(const float2*)&bias[col];
            float2 v0, v1;
            v0.x = acc[mt][nt][0] + bb.x;
            v0.y = acc[mt][nt][1] + bb.y;
            v1.x = acc[mt][nt][2] + bb.x;
            v1.y = acc[mt][nt][3] + bb.y;
            const size_t o0 = (size_t)r0 * N + col;
            const size_t o1 = (size_t)(r0 + 8) * N + col;
            if (resid) {
                float2 rr0 = *(const float2*)&resid[o0];
                float2 rr1 = *(const float2*)&resid[o1];
                v0.x += rr0.x; v0.y += rr0.y;
                v1.x += rr1.x; v1.y += rr1.y;
            }
            if (C32) {
                *(float2*)&C32[o0] = v0;
                *(float2*)&C32[o1] = v1;
            }
            if (C16) {
                *(__half2*)&C16[o0] = h2(v0.x, v0.y);
                *(__half2*)&C16[o1] = h2(v1.x, v1.y);
            }
        }
    }
}

// ---------------------------------------------------------------------------
// RoPE + split + head transpose; fp16 in (qkv), fp16 out, math in fp32.
// ---------------------------------------------------------------------------
__global__ __launch_bounds__(256) void rope_kernel(
    const __half* __restrict__ qkv, const float* __restrict__ freqs,
    __half* __restrict__ Q, __half* __restrict__ K, __half* __restrict__ V)
{
    const int bn = blockIdx.x;
    const int b  = bn >> 11;
    const int h  = threadIdx.x >> 5;
    const int i  = threadIdx.x & 31;
    const int n  = bn & 2047;

    const float f = freqs[(size_t)bn * 32 + i];
    const float c = cosf(f), s = sinf(f);

    const __half* base = qkv + (size_t)bn * 1536;
    const int e = h * 64 + 2 * i;

    const float2 q2 = __half22float2(*(const __half2*)(base + e));
    const float2 k2 = __half22float2(*(const __half2*)(base + 512 + e));
    const __half2 v2 = *(const __half2*)(base + 1024 + e);

    const size_t oidx = (((size_t)(b * NHEAD + h)) * NSEQ + n) * 64 + 2 * i;
    *(__half2*)(Q + oidx) = h2((q2.x * c - q2.y * s) * 0.125f,
                               (q2.x * s + q2.y * c) * 0.125f);
    *(__half2*)(K + oidx) = h2(k2.x * c - k2.y * s, k2.x * s + k2.y * c);
    *(__half2*)(V + oidx) = v2;
}

// ---------------------------------------------------------------------------
// Flash attention, fp16 mma (m16n8k16), FA2 register path (R10, unchanged).
// ---------------------------------------------------------------------------
#define ATT_SMEM ((128 * 72 + 2 * 64 * 72 + 2 * 64 * 72) * 2)

__global__ __launch_bounds__(128) void attn_f16(
    const __half* __restrict__ Qg_, const __half* __restrict__ Kg_,
    const __half* __restrict__ Vg_, __half* __restrict__ O)
{
    extern __shared__ __half hsm[];
    const unsigned uQ = smem_u32(hsm);
    const unsigned uK = uQ + 128 * 72 * 2;
    const unsigned uV = uK + 2 * 64 * 72 * 2;

    const int tid  = threadIdx.x;
    const int warp = tid >> 5;
    const int lane = tid & 31;
    const int g    = lane >> 2;
    const int tg   = lane & 3;
    const int band = warp * 32;

    const int bh    = blockIdx.y;
    const int qbase = blockIdx.x * 128;

    const __half* Qg = Qg_ + ((size_t)bh * NSEQ + qbase) * 64;
    const __half* Kg = Kg_ + (size_t)bh * NSEQ * 64;
    const __half* Vg = Vg_ + (size_t)bh * NSEQ * 64;

    auto prefetchKV = [&](int tile, int s) {
#pragma unroll
        for (int i = 0; i < 4; i++) {
            const int idx = i * 128 + tid;     // 0..511
            const int r   = idx >> 3;          // 0..63
            const int c8  = (idx & 7) << 3;
            const size_t off = (size_t)(tile * 64 + r) * 64 + c8;
            CP_ASYNC_CG(uK + (s * 64 * 72 + r * 72 + c8) * 2, Kg + off);
            CP_ASYNC_CG(uV + (s * 64 * 72 + r * 72 + c8) * 2, Vg + off);
        }
    };

#pragma unroll
    for (int i = 0; i < 8; i++) {
        const int idx = i * 128 + tid;
        const int r   = idx >> 3;
        const int c8  = (idx & 7) << 3;
        CP_ASYNC_CG(uQ + (r * 72 + c8) * 2, Qg + (size_t)r * 64 + c8);
    }
    prefetchKV(0, 0);
    CP_COMMIT();

    unsigned qf[2][4][4];
    float oacc[2][8][4];
#pragma unroll
    for (int mt = 0; mt < 2; mt++)
#pragma unroll
        for (int n = 0; n < 8; n++)
#pragma unroll
            for (int c = 0; c < 4; c++) oacc[mt][n][c] = 0.0f;
    float mst[2][2] = {{-1e30f, -1e30f}, {-1e30f, -1e30f}};
    float lst[2][2] = {{0.0f, 0.0f}, {0.0f, 0.0f}};

    const int NT = NSEQ / 64;
    for (int t = 0; t < NT; t++) {
        __syncthreads();
        if (t + 1 < NT) { prefetchKV(t + 1, (t + 1) & 1); CP_COMMIT(); CP_WAIT(1); }
        else            { CP_WAIT(0); }
        __syncthreads();

        if (t == 0) {
#pragma unroll
            for (int mt = 0; mt < 2; mt++)
#pragma unroll
                for (int ks = 0; ks < 4; ks++) {
                    const int row = band + mt * 16 + (lane & 7) + ((lane >> 3) & 1) * 8;
                    const int col = ks * 16 + (lane >> 4) * 8;
                    LDSM_X4(qf[mt][ks][0], qf[mt][ks][1], qf[mt][ks][2], qf[mt][ks][3],
                            uQ + (row * 72 + col) * 2);
                }
        }

        const unsigned cK = uK + ((t & 1) * 64 * 72) * 2;
        const unsigned cV = uV + ((t & 1) * 64 * 72) * 2;

        // ---- S = Q @ K^T ----
        float sacc[2][8][4];
#pragma unroll
        for (int mt = 0; mt < 2; mt++)
#pragma unroll
            for (int n = 0; n < 8; n++)
#pragma unroll
                for (int c = 0; c < 4; c++) sacc[mt][n][c] = 0.0f;

#pragma unroll
        for (int ks = 0; ks < 4; ks++) {
            unsigned kf[4][4];
#pragma unroll
            for (int kp = 0; kp < 4; kp++) {
                const int row = kp * 16 + (lane & 7) + (lane >> 4) * 8;
                const int col = ks * 16 + ((lane >> 3) & 1) * 8;
                LDSM_X4(kf[kp][0], kf[kp][1], kf[kp][2], kf[kp][3],
                        cK + (row * 72 + col) * 2);
            }
#pragma unroll
            for (int mt = 0; mt < 2; mt++)
#pragma unroll
                for (int n = 0; n < 8; n++)
                    mma16(sacc[mt][n], qf[mt][ks],
                          kf[n >> 1][(n & 1) * 2], kf[n >> 1][(n & 1) * 2 + 1]);
        }

        // ---- online softmax ----
#pragma unroll
        for (int mt = 0; mt < 2; mt++) {
            float r0 = -1e30f, r1 = -1e30f;
#pragma unroll
            for (int n = 0; n < 8; n++) {
                r0 = fmaxf(r0, fmaxf(sacc[mt][n][0], sacc[mt][n][1]));
                r1 = fmaxf(r1, fmaxf(sacc[mt][n][2], sacc[mt][n][3]));
            }
            r0 = fmaxf(r0, __shfl_xor_sync(0xffffffffu, r0, 1));
            r0 = fmaxf(r0, __shfl_xor_sync(0xffffffffu, r0, 2));
            r1 = fmaxf(r1, __shfl_xor_sync(0xffffffffu, r1, 1));
            r1 = fmaxf(r1, __shfl_xor_sync(0xffffffffu, r1, 2));

            const float mn0 = fmaxf(mst[mt][0], r0);
            const float mn1 = fmaxf(mst[mt][1], r1);
            const float c0 = __expf(mst[mt][0] - mn0);
            const float c1 = __expf(mst[mt][1] - mn1);

            float s0 = 0.0f, s1 = 0.0f;
#pragma unroll
            for (int n = 0; n < 8; n++) {
                sacc[mt][n][0] = __expf(sacc[mt][n][0] - mn0);
                sacc[mt][n][1] = __expf(sacc[mt][n][1] - mn0);
                sacc[mt][n][2] = __expf(sacc[mt][n][2] - mn1);
                sacc[mt][n][3] = __expf(sacc[mt][n][3] - mn1);
                s0 += sacc[mt][n][0] + sacc[mt][n][1];
                s1 += sacc[mt][n][2] + sacc[mt][n][3];
            }
            s0 += __shfl_xor_sync(0xffffffffu, s0, 1);
            s0 += __shfl_xor_sync(0xffffffffu, s0, 2);
            s1 += __shfl_xor_sync(0xffffffffu, s1, 1);
            s1 += __shfl_xor_sync(0xffffffffu, s1, 2);

            lst[mt][0] = lst[mt][0] * c0 + s0;
            lst[mt][1] = lst[mt][1] * c1 + s1;
#pragma unroll
            for (int n = 0; n < 8; n++) {
                oacc[mt][n][0] *= c0;  oacc[mt][n][1] *= c0;
                oacc[mt][n][2] *= c1;  oacc[mt][n][3] *= c1;
            }
            mst[mt][0] = mn0;  mst[mt][1] = mn1;
        }

        // ---- O += P @ V ----
#pragma unroll
        for (int ks = 0; ks < 4; ks++) {
            unsigned vf[4][4];
#pragma unroll
            for (int np = 0; np < 4; np++) {
                const int row = ks * 16 + (lane & 7) + ((lane >> 3) & 1) * 8;
                const int col = np * 16 + (lane >> 4) * 8;
                LDSM_X4_T(vf[np][0], vf[np][1], vf[np][2], vf[np][3],
                          cV + (row * 72 + col) * 2);
            }
#pragma unroll
            for (int mt = 0; mt < 2; mt++) {
                unsigned pf[4];
                pf[0] = pack_h2(sacc[mt][2 * ks][0],     sacc[mt][2 * ks][1]);
                pf[1] = pack_h2(sacc[mt][2 * ks][2],     sacc[mt][2 * ks][3]);
                pf[2] = pack_h2(sacc[mt][2 * ks + 1][0], sacc[mt][2 * ks + 1][1]);
                pf[3] = pack_h2(sacc[mt][2 * ks + 1][2], sacc[mt][2 * ks + 1][3]);
#pragma unroll
                for (int n = 0; n < 8; n++)
                    mma16(oacc[mt][n], pf,
                          vf[n >> 1][(n & 1) * 2], vf[n >> 1][(n & 1) * 2 + 1]);
            }
        }
    }

    // ---- epilogue ----
    const int b = bh >> 3;
    const int h = bh & 7;
#pragma unroll
    for (int mt = 0; mt < 2; mt++) {
        const float inv0 = 1.0f / lst[mt][0];
        const float inv1 = 1.0f / lst[mt][1];
        const int r0 = qbase + band + mt * 16 + g;
        __half* O0 = O + ((size_t)(b * NSEQ) + r0) * DIM + h * 64;
        __half* O1 = O + ((size_t)(b * NSEQ) + r0 + 8) * DIM + h * 64;
#pragma unroll
        for (int n = 0; n < 8; n++) {
            const int c = n * 8 + tg * 2;
            *(__half2*)&O0[c] = h2(oacc[mt][n][0] * inv0, oacc[mt][n][1] * inv0);
            *(__half2*)&O1[c] = h2(oacc[mt][n][2] * inv1, oacc[mt][n][3] * inv1);
        }
    }
}

// ---------------------------------------------------------------------------
// LayerNorm (over 1024) + exact GELU; fp16 in, fp16 out, in place.
// Stats accumulated in fp32.
// ---------------------------------------------------------------------------
__device__ __forceinline__ float gelu_exact(float x) {
    return 0.5f * x * (1.0f + erff(x * 0.70710678118654752440f));
}

__global__ __launch_bounds__(256) void ln_gelu_kernel(
    __half* __restrict__ hc,
    const float* __restrict__ gam, const float* __restrict__ bet)
{
    const int row = blockIdx.x;
    __half* p = hc + (size_t)row * 1024;
    const int tid = threadIdx.x;

    const uint2 raw = *(const uint2*)(p + tid * 4);
    const float2 ab = __half22float2(*(const __half2*)&raw.x);
    const float2 cd = __half22float2(*(const __half2*)&raw.y);

    float s  = ab.x + ab.y + cd.x + cd.y;
    float ss = ab.x * ab.x + ab.y * ab.y + cd.x * cd.x + cd.y * cd.y;

#pragma unroll
    for (int off = 16; off > 0; off >>= 1) {
        s  += __shfl_xor_sync(0xffffffffu, s,  off);
        ss += __shfl_xor_sync(0xffffffffu, ss, off);
    }

    __shared__ float rs[8], rss[8];
    __shared__ float s_mean, s_rstd;
    const int wid = tid >> 5, lane = tid & 31;
    if (lane == 0) { rs[wid] = s; rss[wid] = ss; }
    __syncthreads();
    if (tid == 0) {
        float S = 0.0f, SS = 0.0f;
#pragma unroll
        for (int w = 0; w < 8; w++) { S += rs[w]; SS += rss[w]; }
        const float mean = S * (1.0f / 1024.0f);
        const float var  = SS * (1.0f / 1024.0f) - mean * mean;
        s_mean = mean;
        s_rstd = rsqrtf(var + 1e-5f);
    }
    __syncthreads();

    const float mean = s_mean, rstd = s_rstd;
    const int col = tid * 4;
    float a = gelu_exact((ab.x - mean) * rstd * gam[col]     + bet[col]);
    float b = gelu_exact((ab.y - mean) * rstd * gam[col + 1] + bet[col + 1]);
    float c = gelu_exact((cd.x - mean) * rstd * gam[col + 2] + bet[col + 2]);
    float d = gelu_exact((cd.y - mean) * rstd * gam[col + 3] + bet[col + 3]);
    *(__half2*)(p + col)     = h2(a, b);
    *(__half2*)(p + col + 2) = h2(c, d);
}

// ---------------------------------------------------------------------------
extern "C" void kernel_launch(void* const* d_in, const int* in_sizes, int n_in,
                              void* d_out, int out_size)
{
    const float* x      = (const float*)d_in[0];
    const float* freqs  = (const float*)d_in[1];
    const float* wqkv_w = (const float*)d_in[2];
    const float* wqkv_b = (const float*)d_in[3];
    const float* out_w  = (const float*)d_in[4];
    const float* out_b  = (const float*)d_in[5];
    const float* ffn1_w = (const float*)d_in[6];
    const float* ffn1_b = (const float*)d_in[7];
    const float* ln_g   = (const float*)d_in[8];
    const float* ln_b   = (const float*)d_in[9];
    const float* ffn2_w = (const float*)d_in[10];
    const float* ffn2_b = (const float*)d_in[11];
    float* out = (float*)d_out;

    __half *qkvh, *xh, *wqkvh, *outwh, *ffn1h, *ffn2h;
    __half *qh, *kh, *vh, *atth, *msgh, *hcath;
    cudaGetSymbolAddress((void**)&qkvh,  g_qkvh);
    cudaGetSymbolAddress((void**)&xh,    g_xh);
    cudaGetSymbolAddress((void**)&wqkvh, g_wqkvh);
    cudaGetSymbolAddress((void**)&outwh, g_outwh);
    cudaGetSymbolAddress((void**)&ffn1h, g_ffn1h);
    cudaGetSymbolAddress((void**)&ffn2h, g_ffn2h);
    cudaGetSymbolAddress((void**)&qh,    g_qh);
    cudaGetSymbolAddress((void**)&kh,    g_kh);
    cudaGetSymbolAddress((void**)&vh,    g_vh);
    cudaGetSymbolAddress((void**)&atth,  g_atth);
    cudaGetSymbolAddress((void**)&msgh,  g_msgh);
    cudaGetSymbolAddress((void**)&hcath, g_hcath);

    cudaFuncSetAttribute(gemm_f16, cudaFuncAttributeMaxDynamicSharedMemorySize, GSMEM);
    cudaFuncSetAttribute(attn_f16, cudaFuncAttributeMaxDynamicSharedMemorySize, ATT_SMEM);

    // 0) Single fused fp32 -> fp16 convert (x + all weights)
    cvt_all_kernel<<<SEG_W3 / 256, 256>>>(
        x, wqkv_w, out_w, ffn1_w, ffn2_w, xh, wqkvh, outwh, ffn1h, ffn2h);

    // 1) QKV projection -> fp16 qkv (RoPE input)
    gemm_f16<<<dim3(1536 / 128, ROWS / 128), 256, GSMEM>>>(
        xh, DIM, xh, DIM, 512, wqkvh, wqkv_b, nullptr, nullptr, qkvh, 1536, 512);

    // 2) RoPE + head transpose -> fp16 Q/K/V
    rope_kernel<<<ROWS, 256>>>(qkvh, freqs, qh, kh, vh);

    // 3) Attention -> fp16 att [B,N,D]
    attn_f16<<<dim3(NSEQ / 128, BATCH * NHEAD), 128, ATT_SMEM>>>(qh, kh, vh, atth);

    // 4) Out projection -> fp16 msg
    gemm_f16<<<dim3(512 / 128, ROWS / 128), 256, GSMEM>>>(
        atth, DIM, atth, DIM, 512, outwh, out_b, nullptr, nullptr, msgh, 512, 512);

    // 5) FFN1 over concat([x, msg]) -> fp16 hcat
    gemm_f16<<<dim3(1024 / 128, ROWS / 128), 256, GSMEM>>>(
        xh, DIM, msgh, DIM, 512, ffn1h, ffn1_b, nullptr, nullptr, hcath, 1024, 1024);

    // 6) LayerNorm + GELU, fp16 in place
    ln_gelu_kernel<<<ROWS, 256>>>(hcath, ln_g, ln_b);

    // 7) FFN2 + residual x -> fp32 out
    gemm_f16<<<dim3(512 / 128, ROWS / 128), 256, GSMEM>>>(
        hcath, 2 * DIM, hcath, 2 * DIM, 1024, ffn2h, ffn2_b, x, out, nullptr, 512, 1024);
}